// round 2
// baseline (speedup 1.0000x reference)
#include <cuda_runtime.h>
#include <cstdint>

#define NQ      12
#define DIM     4096      // 2^12 amplitudes
#define THREADS 256
#define BATCH   4096
#define FEAT    768
#define NCLASS  10
#define DEPTH   3

// GF(2) bookkeeping for the (compile-time-fixed) CNOT ring structure.
// c0col/c1col: columns of the layer-0/1 CNOT composite C (scatter dst = C*y)
// mrow[q]    : row (11-q) of layer-2 composite  (measurement parity mask per wire)
struct GF2Args {
    int c0col[12];
    int c1col[12];
    int mrow[12];
};

// apply 4 complex 2x2 gates (local bits 0..3 of the 16-amp register block)
template <int STAGE>
__device__ __forceinline__ void apply4(float2 amp[16], const float (&rotm)[36][8], int l) {
#pragma unroll
    for (int g = 0; g < 4; ++g) {
        const int wire = 11 - (STAGE * 4 + g);
        const float* m = rotm[l * 12 + wire];
        const float m00r = m[0], m00i = m[1], m01r = m[2], m01i = m[3];
        const float m10r = m[4], m10i = m[5], m11r = m[6], m11i = m[7];
        const int mask = 1 << g;
#pragma unroll
        for (int k = 0; k < 8; ++k) {
            const int h  = ((k & ~(mask - 1)) << 1) | (k & (mask - 1));
            const int h2 = h | mask;
            const float2 a = amp[h], b = amp[h2];
            amp[h].x  = m00r * a.x - m00i * a.y + m01r * b.x - m01i * b.y;
            amp[h].y  = m00r * a.y + m00i * a.x + m01r * b.y + m01i * b.x;
            amp[h2].x = m10r * a.x - m10i * a.y + m11r * b.x - m11i * b.y;
            amp[h2].y = m10r * a.y + m10i * a.x + m11r * b.y + m11i * b.x;
        }
    }
}

__global__ __launch_bounds__(THREADS)
void qhead_kernel(const float* __restrict__ x,
                  const float* __restrict__ Wp,
                  const float* __restrict__ weights,
                  const float* __restrict__ Wo,
                  const float* __restrict__ bo,
                  float* __restrict__ out,
                  GF2Args g)
{
    __shared__ float2 st[DIM];          // swizzled state: slot(p) = p ^ ((p>>4)&15)
    __shared__ float2 cs[NQ];           // (cos(th/2), sin(th/2)) per wire
    __shared__ float  rotm[36][8];      // 36 Rot matrices (complex 2x2)
    __shared__ float  red[8][NQ];       // cross-warp reduction buffer

    const int t    = threadIdx.x;
    const int b    = blockIdx.x;
    const int lane = t & 31;
    const int warp = t >> 5;

    // ---- angle encoding: 12 dot products of length 768, tanh, half-angle sincos ----
    {
        const float* xr = x + (size_t)b * FEAT;
        const int q0 = warp;
        const bool two = (warp < 4);
        const float* wp0 = Wp + q0 * FEAT;
        const float* wp1 = Wp + (q0 + 8) * FEAT;
        float d0 = 0.f, d1 = 0.f;
        for (int i = lane; i < FEAT; i += 32) {
            const float xv = xr[i];
            d0 += xv * wp0[i];
            if (two) d1 += xv * wp1[i];
        }
#pragma unroll
        for (int o = 16; o; o >>= 1) {
            d0 += __shfl_xor_sync(0xffffffffu, d0, o);
            d1 += __shfl_xor_sync(0xffffffffu, d1, o);
        }
        if (lane == 0) {
            // theta/2 = tanh(dot) * pi/4
            float th = tanhf(d0) * 0.7853981633974483f;
            float c, s; __sincosf(th, &s, &c);
            cs[q0] = make_float2(c, s);
            if (two) {
                float th1 = tanhf(d1) * 0.7853981633974483f;
                float c1, s1; __sincosf(th1, &s1, &c1);
                cs[q0 + 8] = make_float2(c1, s1);
            }
        }
    }

    // ---- Rot matrices: Rot(phi,theta,omega) = RZ(om) RY(th) RZ(phi) ----
    if (t < 36) {
        const float phi = weights[t * 3 + 0];
        const float th  = weights[t * 3 + 1];
        const float om  = weights[t * 3 + 2];
        float c, s; __sincosf(0.5f * th, &s, &c);
        const float aa = 0.5f * (phi + om);
        const float bb = 0.5f * (phi - om);
        float sa, ca, sb, cb;
        __sincosf(aa, &sa, &ca);
        __sincosf(bb, &sb, &cb);
        rotm[t][0] =  c * ca;  rotm[t][1] = -c * sa;   // m00 = e^{-i a} c
        rotm[t][2] = -s * cb;  rotm[t][3] = -s * sb;   // m01 = -e^{+i b} s
        rotm[t][4] =  s * cb;  rotm[t][5] = -s * sb;   // m10 =  e^{-i b} s
        rotm[t][6] =  c * ca;  rotm[t][7] =  c * sa;   // m11 = e^{+i a} c
    }
    __syncthreads();

    // ---- init product state (pattern C: p = v*256 + t; bit j of p <-> wire 11-j) ----
    {
        float base = 1.f;
#pragma unroll
        for (int j = 0; j < 8; ++j) {
            const float2 csv = cs[11 - j];
            base *= ((t >> j) & 1) ? csv.y : csv.x;
        }
        const float2 f8 = cs[3], f9 = cs[2], f10 = cs[1], f11 = cs[0];
        const int slo = t ^ (t >> 4);
#pragma unroll
        for (int v = 0; v < 16; ++v) {
            float f = base;
            f *= (v & 1) ? f8.y  : f8.x;
            f *= (v & 2) ? f9.y  : f9.x;
            f *= (v & 4) ? f10.y : f10.x;
            f *= (v & 8) ? f11.y : f11.x;
            st[v * 256 + slo] = make_float2(f, 0.f);
        }
    }
    __syncthreads();

    float2 amp[16];

#pragma unroll 1
    for (int l = 0; l < DEPTH; ++l) {
        // ---- stage A: bits 0-3 (wires 11..8). slot = t*16 + (v ^ (t&15)) ----
        {
            const int base = t * 16, x4 = t & 15;
#pragma unroll
            for (int v = 0; v < 16; ++v) amp[v] = st[base + (v ^ x4)];
            apply4<0>(amp, rotm, l);
#pragma unroll
            for (int v = 0; v < 16; ++v) st[base + (v ^ x4)] = amp[v];
        }
        __syncthreads();

        // ---- stage B: bits 4-7 (wires 7..4). slot = (t>>4)*256 + v*16 + ((t&15)^v) ----
        {
            const int hi = (t >> 4) * 256, x4 = t & 15;
#pragma unroll
            for (int v = 0; v < 16; ++v) amp[v] = st[hi + v * 16 + (x4 ^ v)];
            apply4<1>(amp, rotm, l);
#pragma unroll
            for (int v = 0; v < 16; ++v) st[hi + v * 16 + (x4 ^ v)] = amp[v];
        }
        __syncthreads();

        // ---- stage C: bits 8-11 (wires 3..0). slot = v*256 + (t ^ (t>>4)) ----
        {
            const int slo = t ^ (t >> 4);
#pragma unroll
            for (int v = 0; v < 16; ++v) amp[v] = st[v * 256 + slo];
            apply4<2>(amp, rotm, l);
            if (l < 2) {
                // CNOT layer as a free relabeling: scatter new[C*y] = cur[y]
                __syncthreads();
                const int* col = (l == 0) ? g.c0col : g.c1col;
                int dT = 0;
#pragma unroll
                for (int j = 0; j < 8; ++j) dT ^= ((t >> j) & 1) ? col[j] : 0;
                const int c8 = col[8], c9 = col[9], c10 = col[10], c11 = col[11];
#pragma unroll
                for (int v = 0; v < 16; ++v) {
                    int dst = dT ^ ((v & 1) ? c8 : 0) ^ ((v & 2) ? c9 : 0)
                                 ^ ((v & 4) ? c10 : 0) ^ ((v & 8) ? c11 : 0);
                    st[dst ^ ((dst >> 4) & 15)] = amp[v];
                }
                __syncthreads();
            }
            // l == 2: keep amps in registers for measurement (final CNOTs folded
            // into the measurement parity masks)
        }
    }

    // ---- PauliZ expectations (amps at p = v*256 + t, logical bit via GF(2) parity) ----
    float acc[NQ];
#pragma unroll
    for (int q = 0; q < NQ; ++q) acc[q] = 0.f;
    unsigned tab[NQ];
#pragma unroll
    for (int q = 0; q < NQ; ++q) {
        const int row = g.mrow[q];
        const int hi = (row >> 8) & 15;
        unsigned tb = 0;
        if (hi & 1) tb ^= 0xAAAAu;
        if (hi & 2) tb ^= 0xCCCCu;
        if (hi & 4) tb ^= 0xF0F0u;
        if (hi & 8) tb ^= 0xFF00u;
        if (__popc(row & t) & 1) tb = ~tb;
        tab[q] = tb;
    }
#pragma unroll
    for (int v = 0; v < 16; ++v) {
        const float2 a = amp[v];
        const float p  = a.x * a.x + a.y * a.y;
        const float np = -p;
#pragma unroll
        for (int q = 0; q < NQ; ++q)
            acc[q] += ((tab[q] >> v) & 1) ? np : p;
    }
#pragma unroll
    for (int q = 0; q < NQ; ++q) {
        float vq = acc[q];
#pragma unroll
        for (int o = 16; o; o >>= 1) vq += __shfl_xor_sync(0xffffffffu, vq, o);
        if (lane == 0) red[warp][q] = vq;
    }
    __syncthreads();

    // ---- output head: out[b][c] = bo[c] + sum_q z[q] * Wo[c][q] ----
    if (t < NCLASS) {
        float o = bo[t];
#pragma unroll
        for (int q = 0; q < NQ; ++q) {
            float z = 0.f;
#pragma unroll
            for (int w = 0; w < 8; ++w) z += red[w][q];
            o += z * Wo[t * NQ + q];
        }
        out[(size_t)b * NCLASS + t] = o;
    }
}

// ---- host: build GF(2) composites of the fixed CNOT rings (r = 1,2,3) ----
static void build_gf2(GF2Args& a) {
    int rows[12], cols[12];
    for (int l = 0; l < 3; ++l) {
        for (int j = 0; j < 12; ++j) { rows[j] = 1 << j; cols[j] = 1 << j; }
        const int r = l % 11 + 1;
        for (int q = 0; q < 12; ++q) {
            const int c = q, tg = (q + r) % 12;
            const int bc = 11 - c, bt = 11 - tg;
            rows[bt] ^= rows[bc];                         // comp <- E * comp (rows)
            for (int j = 0; j < 12; ++j)                  // columns of E * comp
                if ((cols[j] >> bc) & 1) cols[j] ^= (1 << bt);
        }
        if (l == 0) for (int j = 0; j < 12; ++j) a.c0col[j] = cols[j];
        if (l == 1) for (int j = 0; j < 12; ++j) a.c1col[j] = cols[j];
        if (l == 2) for (int q = 0; q < 12; ++q) a.mrow[q] = rows[11 - q];
    }
}

extern "C" void kernel_launch(void* const* d_in, const int* in_sizes, int n_in,
                              void* d_out, int out_size) {
    (void)in_sizes; (void)n_in; (void)out_size;
    const float* x       = (const float*)d_in[0];
    const float* Wp      = (const float*)d_in[1];
    const float* weights = (const float*)d_in[2];
    const float* Wo      = (const float*)d_in[3];
    const float* bo      = (const float*)d_in[4];

    GF2Args g;
    build_gf2(g);

    qhead_kernel<<<BATCH, THREADS>>>(x, Wp, weights, Wo, bo, (float*)d_out, g);
}